// round 10
// baseline (speedup 1.0000x reference)
#include <cuda_runtime.h>
#include <cuda_bf16.h>
#include <cstdint>

#define D_FEAT    128
#define OUT_DIM   128
#define MAX_NODES 100000
#define MAX_EDGES 600000
#define CNT_PAD   102400

#define TM   128          // rows per GEMM tile
#define CK   128          // K per chunk (2 chunks: h then x)
#define LDA  136          // padded bf16 row (272 B stride)
#define GT   256          // GEMM threads (8 warps)

#define CSR_BLK 1024

// ---- device scratch (allocation-free) ----
__device__ float g_h[(size_t)MAX_NODES * D_FEAT];
__device__ __align__(16) int g_cnt[CNT_PAD];   // zero-init; self-cleaned each run
__device__ int   g_off[MAX_NODES + 1];
__device__ int   g_cur[MAX_NODES];
__device__ int   g_bsum[128];
__device__ int2  g_edge[MAX_EDGES];
__device__ int   g_bar_cnt;                    // grid barrier state (zero-init)
__device__ int   g_bar_gen;
// bf16 hi/lo images of B chunks: [chunk][part][n=128][k padded to LDA]
__device__ uint4 g_Bimg4[2 * 4352];   // 2 x 69632 B

// ============================ PTX helpers =================================
__device__ __forceinline__ uint32_t smem_u32(const void* p) {
    uint32_t a;
    asm("{ .reg .u64 t; cvta.to.shared.u64 t, %1; cvt.u32.u64 %0, t; }" : "=r"(a) : "l"(p));
    return a;
}
__device__ __forceinline__ void ldsm4(uint32_t* r, uint32_t addr) {
    asm volatile("ldmatrix.sync.aligned.m8n8.x4.shared.b16 {%0,%1,%2,%3}, [%4];"
                 : "=r"(r[0]), "=r"(r[1]), "=r"(r[2]), "=r"(r[3]) : "r"(addr));
}
__device__ __forceinline__ void mma_bf16(float* d, const uint32_t* a,
                                         uint32_t b0, uint32_t b1) {
    asm volatile(
        "mma.sync.aligned.m16n8k16.row.col.f32.bf16.bf16.f32 "
        "{%0,%1,%2,%3}, {%4,%5,%6,%7}, {%8,%9}, {%0,%1,%2,%3};"
        : "+f"(d[0]), "+f"(d[1]), "+f"(d[2]), "+f"(d[3])
        : "r"(a[0]), "r"(a[1]), "r"(a[2]), "r"(a[3]), "r"(b0), "r"(b1));
}
__device__ __forceinline__ uint32_t bf16x2(float y, float x) {
    uint32_t r; asm("cvt.rn.bf16x2.f32 %0, %1, %2;" : "=r"(r) : "f"(y), "f"(x)); return r;
}
__device__ __forceinline__ void cpa16(uint32_t dst, const void* src) {
    asm volatile("cp.async.cg.shared.global [%0], [%1], 16;" :: "r"(dst), "l"(src));
}
__device__ __forceinline__ void cpa16z(uint32_t dst, const void* src, int valid) {
    int sz = valid ? 16 : 0;
    asm volatile("cp.async.cg.shared.global [%0], [%1], 16, %2;"
                 :: "r"(dst), "l"(src), "r"(sz));
}
__device__ __forceinline__ void cpa_commit() {
    asm volatile("cp.async.commit_group;" ::: "memory");
}
template <int N>
__device__ __forceinline__ void cpa_wait() {
    asm volatile("cp.async.wait_group %0;" :: "n"(N) : "memory");
}

// ---- software grid barrier (all blocks co-resident: nb <= 148) ----
__device__ __forceinline__ void grid_bar(int nb) {
    __syncthreads();
    if (threadIdx.x == 0) {
        __threadfence();
        int gen = *(volatile int*)&g_bar_gen;
        if (atomicAdd(&g_bar_cnt, 1) == nb - 1) {
            g_bar_cnt = 0;
            __threadfence();
            *(volatile int*)&g_bar_gen = gen + 1;
        } else {
            while (*(volatile int*)&g_bar_gen == gen) { }
        }
        __threadfence();
    }
    __syncthreads();
}

// ====== fused CSR build: B-prep + hist | scan | offsets | scatter ==========
__global__ __launch_bounds__(CSR_BLK, 1)
void csr_build_kernel(const int*   __restrict__ rows,
                      const int*   __restrict__ cols,
                      const float* __restrict__ vals,
                      const float* __restrict__ W,
                      int n, int n_edges, int nb) {
    __shared__ int wsum[32];
    __shared__ int sbase;
    const int t    = threadIdx.x;
    const int lane = t & 31;
    const int w    = t >> 5;
    const int gid  = blockIdx.x * CSR_BLK + t;
    const int NT   = nb * CSR_BLK;

    // ---- phase 1: B image prep + edge histogram ----
    if (gid < 2 * 128 * 128) {
        int c = gid >> 14;
        int r = gid & 16383;
        int k = r >> 7;
        int nn = r & 127;
        float wv = W[(size_t)(c * 128 + k) * OUT_DIM + nn];
        __nv_bfloat16 hb = __float2bfloat16(wv);
        __nv_bfloat16 lb = __float2bfloat16(wv - __bfloat162float(hb));
        __nv_bfloat16* img = (__nv_bfloat16*)g_Bimg4;
        img[(((size_t)c * 2 + 0) * 128 + nn) * LDA + k] = hb;
        img[(((size_t)c * 2 + 1) * 128 + nn) * LDA + k] = lb;
    }
    for (int e = gid; e < n_edges; e += NT)
        atomicAdd(&g_cnt[rows[e]], 1);

    grid_bar(nb);

    // ---- phase 2: block-local inclusive scan + publish block total ----
    int i = blockIdx.x * CSR_BLK + t;
    int v = (i < n) ? g_cnt[i] : 0;
    int s = v;
#pragma unroll
    for (int d = 1; d < 32; d <<= 1) {
        int q = __shfl_up_sync(~0u, s, d);
        if (lane >= d) s += q;
    }
    if (lane == 31) wsum[w] = s;
    __syncthreads();
    if (w == 0) {
        int q = wsum[lane];
#pragma unroll
        for (int d = 1; d < 32; d <<= 1) {
            int r = __shfl_up_sync(~0u, q, d);
            if (lane >= d) q += r;
        }
        wsum[lane] = q;
    }
    __syncthreads();
    int wbase = (w > 0) ? wsum[w - 1] : 0;
    int s_incl = wbase + s;                      // inclusive over block
    if (t == CSR_BLK - 1) g_bsum[blockIdx.x] = s_incl;

    grid_bar(nb);

    // ---- base = sum of earlier block totals; write offsets/cursors ----
    if (w == 0) {
        int b = 0;
        for (int j = lane; j < (int)blockIdx.x; j += 32) b += g_bsum[j];
#pragma unroll
        for (int o = 16; o > 0; o >>= 1) b += __shfl_xor_sync(~0u, b, o);
        if (lane == 0) sbase = b;
    }
    __syncthreads();
    if (i < n) {
        int o = sbase + s_incl - v;
        g_off[i] = o;
        g_cur[i] = o;
        g_cnt[i] = 0;          // self-clean for next launch
    }
    if (i == n) g_off[n] = n_edges;

    grid_bar(nb);

    // ---- phase 3: scatter permute ----
#pragma unroll 2
    for (int e = gid; e < n_edges; e += NT) {
        int r = rows[e];
        int p = atomicAdd(&g_cur[r], 1);
        g_edge[p] = make_int2(cols[e], __float_as_int(vals[e]));
    }
}

// ============ SpMM: warp per row, full occupancy, x4 unrolled ==============
__global__ void spmm_csr_kernel(const float* __restrict__ x, int n_nodes) {
    int row  = (blockIdx.x * blockDim.x + threadIdx.x) >> 5;
    int lane = threadIdx.x & 31;
    if (row >= n_nodes) return;

    int e  = g_off[row];
    int e1 = g_off[row + 1];

    float4 aA = make_float4(0.f, 0.f, 0.f, 0.f);
    float4 aB = make_float4(0.f, 0.f, 0.f, 0.f);
    for (; e + 4 <= e1; e += 4) {
        int2 e0 = g_edge[e],     e1v = g_edge[e + 1];
        int2 e2 = g_edge[e + 2], e3v = g_edge[e + 3];
        float4 x0 = ((const float4*)(x + (size_t)e0.x  * D_FEAT))[lane];
        float4 x1 = ((const float4*)(x + (size_t)e1v.x * D_FEAT))[lane];
        float4 x2 = ((const float4*)(x + (size_t)e2.x  * D_FEAT))[lane];
        float4 x3 = ((const float4*)(x + (size_t)e3v.x * D_FEAT))[lane];
        float v0 = __int_as_float(e0.y),  v1 = __int_as_float(e1v.y);
        float v2 = __int_as_float(e2.y),  v3 = __int_as_float(e3v.y);
        aA.x = fmaf(v0, x0.x, aA.x); aA.y = fmaf(v0, x0.y, aA.y);
        aA.z = fmaf(v0, x0.z, aA.z); aA.w = fmaf(v0, x0.w, aA.w);
        aB.x = fmaf(v1, x1.x, aB.x); aB.y = fmaf(v1, x1.y, aB.y);
        aB.z = fmaf(v1, x1.z, aB.z); aB.w = fmaf(v1, x1.w, aB.w);
        aA.x = fmaf(v2, x2.x, aA.x); aA.y = fmaf(v2, x2.y, aA.y);
        aA.z = fmaf(v2, x2.z, aA.z); aA.w = fmaf(v2, x2.w, aA.w);
        aB.x = fmaf(v3, x3.x, aB.x); aB.y = fmaf(v3, x3.y, aB.y);
        aB.z = fmaf(v3, x3.z, aB.z); aB.w = fmaf(v3, x3.w, aB.w);
    }
    for (; e < e1; e++) {
        int2 ev = g_edge[e];
        float4 xv = ((const float4*)(x + (size_t)ev.x * D_FEAT))[lane];
        float v = __int_as_float(ev.y);
        aA.x = fmaf(v, xv.x, aA.x); aA.y = fmaf(v, xv.y, aA.y);
        aA.z = fmaf(v, xv.z, aA.z); aA.w = fmaf(v, xv.w, aA.w);
    }
    float4 acc = make_float4(aA.x + aB.x, aA.y + aB.y, aA.z + aB.z, aA.w + aB.w);
    ((float4*)(g_h + (size_t)row * D_FEAT))[lane] = acc;
}

// ====== GEMM: out = relu([h|x] @ W), cp.async pipelined, 8 warps ==========
// smem: A hi (34816) | A lo (34816) | B hi+lo (69632) | x fp32 scratch (65536)
#define SM_A     0
#define SM_PART  34816
#define SM_B     69632
#define SM_X     139264
#define SM_TOTAL 204800

__global__ __launch_bounds__(GT, 1)
void gemm_mma_kernel(const float* __restrict__ x,
                     float* __restrict__ out,
                     int n_nodes) {
    extern __shared__ char smem[];
    const uint32_t sbase = smem_u32(smem);
    const int tid  = threadIdx.x;
    const int wid  = tid >> 5;
    const int lane = tid & 31;
    const int wm   = wid >> 1;       // 0..3  (32-row strip)
    const int wn   = wid & 1;        // 0..1  (64-col strip)
    const int row0 = blockIdx.x * TM;

    uint32_t pA[2], pB[4];
#pragma unroll
    for (int mf = 0; mf < 2; mf++)
        pA[mf] = sbase + SM_A
               + (uint32_t)((wm * 32 + mf * 16 + (lane & 15)) * (LDA * 2))
               + (uint32_t)((lane >> 4) << 4);
#pragma unroll
    for (int p = 0; p < 4; p++)
        pB[p] = sbase + SM_B
              + (uint32_t)((wn * 64 + p * 16 + (lane & 7) + ((lane >> 4) << 3)) * (LDA * 2))
              + (uint32_t)((lane & 8) << 1);

    float acc[2][8][4];
#pragma unroll
    for (int mf = 0; mf < 2; mf++)
#pragma unroll
        for (int nf = 0; nf < 8; nf++)
#pragma unroll
            for (int q = 0; q < 4; q++) acc[mf][nf][q] = 0.f;

    // ---- group 0: B chunk-0 image via cp.async ----
    {
        const uint4* sB = g_Bimg4;
#pragma unroll
        for (int j = tid; j < 4352; j += GT)
            cpa16(sbase + SM_B + j * 16, sB + j);
    }
    cpa_commit();
    // ---- group 1: x rows (chunk 1) fp32 -> scratch via cp.async ----
    {
#pragma unroll
        for (int j = 0; j < 4096 / GT; j++) {
            int i  = tid + j * GT;
            int r  = i >> 5;
            int kq = i & 31;
            int gr = row0 + r;
            cpa16z(sbase + SM_X + (uint32_t)(r * 512 + kq * 16),
                   x + (size_t)gr * D_FEAT + kq * 4, gr < n_nodes);
        }
    }
    cpa_commit();

    // ---- stage A chunk 0 from g_h (fp32 load, split bf16 hi/lo) ----
#pragma unroll
    for (int j = 0; j < (TM * CK / 4) / GT; j++) {
        int i  = tid + j * GT;
        int r  = i >> 5;
        int kq = i & 31;
        int gr = row0 + r;
        float4 v = make_float4(0.f, 0.f, 0.f, 0.f);
        if (gr < n_nodes) v = ((const float4*)(g_h + (size_t)gr * D_FEAT))[kq];
        uint32_t h01 = bf16x2(v.y, v.x);
        uint32_t h23 = bf16x2(v.w, v.z);
        float fx = __uint_as_float(h01 << 16);
        float fy = __uint_as_float(h01 & 0xffff0000u);
        float fz = __uint_as_float(h23 << 16);
        float fw = __uint_as_float(h23 & 0xffff0000u);
        uint32_t l01 = bf16x2(v.y - fy, v.x - fx);
        uint32_t l23 = bf16x2(v.w - fw, v.z - fz);
        char* dst = smem + SM_A + r * (LDA * 2) + kq * 8;
        *(uint2*)dst             = make_uint2(h01, h23);
        *(uint2*)(dst + SM_PART) = make_uint2(l01, l23);
    }
    cpa_wait<1>();
    __syncthreads();

    for (int c = 0; c < 2; c++) {
#pragma unroll
        for (int ks = 0; ks < CK / 16; ks++) {
            const uint32_t k0b = (uint32_t)(ks << 5);
            uint32_t Ah[2][4], Al[2][4];
#pragma unroll
            for (int mf = 0; mf < 2; mf++) {
                ldsm4(Ah[mf], pA[mf] + k0b);
                ldsm4(Al[mf], pA[mf] + SM_PART + k0b);
            }
            uint32_t Bh[4][4], Bl[4][4];
#pragma unroll
            for (int p = 0; p < 4; p++) {
                ldsm4(Bh[p], pB[p] + k0b);
                ldsm4(Bl[p], pB[p] + SM_PART + k0b);
            }
#pragma unroll
            for (int mf = 0; mf < 2; mf++)
#pragma unroll
                for (int p = 0; p < 4; p++) {
                    mma_bf16(acc[mf][2 * p],     Ah[mf], Bh[p][0], Bh[p][1]);
                    mma_bf16(acc[mf][2 * p + 1], Ah[mf], Bh[p][2], Bh[p][3]);
                    mma_bf16(acc[mf][2 * p],     Al[mf], Bh[p][0], Bh[p][1]);
                    mma_bf16(acc[mf][2 * p + 1], Al[mf], Bh[p][2], Bh[p][3]);
                    mma_bf16(acc[mf][2 * p],     Ah[mf], Bl[p][0], Bl[p][1]);
                    mma_bf16(acc[mf][2 * p + 1], Ah[mf], Bl[p][2], Bl[p][3]);
                }
        }

        if (c == 0) {
            cpa_wait<0>();
            __syncthreads();

            {
                const uint4* sB = g_Bimg4 + 4352;
#pragma unroll
                for (int j = tid; j < 4352; j += GT)
                    cpa16(sbase + SM_B + j * 16, sB + j);
            }
            cpa_commit();

#pragma unroll
            for (int j = 0; j < (TM * CK / 4) / GT; j++) {
                int i  = tid + j * GT;
                int r  = i >> 5;
                int kq = i & 31;
                float4 v = *(const float4*)(smem + SM_X + r * 512 + kq * 16);
                uint32_t h01 = bf16x2(v.y, v.x);
                uint32_t h23 = bf16x2(v.w, v.z);
                float fx = __uint_as_float(h01 << 16);
                float fy = __uint_as_float(h01 & 0xffff0000u);
                float fz = __uint_as_float(h23 << 16);
                float fw = __uint_as_float(h23 & 0xffff0000u);
                uint32_t l01 = bf16x2(v.y - fy, v.x - fx);
                uint32_t l23 = bf16x2(v.w - fw, v.z - fz);
                char* dst = smem + SM_A + r * (LDA * 2) + kq * 8;
                *(uint2*)dst             = make_uint2(h01, h23);
                *(uint2*)(dst + SM_PART) = make_uint2(l01, l23);
            }
            cpa_wait<0>();
            __syncthreads();
        }
    }

    // ---- epilogue: relu + store ----
#pragma unroll
    for (int mf = 0; mf < 2; mf++) {
        int gr0 = row0 + wm * 32 + mf * 16 + (lane >> 2);
#pragma unroll
        for (int nf = 0; nf < 8; nf++) {
            int col = wn * 64 + (nf >> 1) * 16 + (nf & 1) * 8 + (lane & 3) * 2;
            float* a = acc[mf][nf];
            if (gr0 < n_nodes) {
                float2 o0 = make_float2(fmaxf(a[0], 0.f), fmaxf(a[1], 0.f));
                *(float2*)(out + (size_t)gr0 * OUT_DIM + col) = o0;
            }
            if (gr0 + 8 < n_nodes) {
                float2 o1 = make_float2(fmaxf(a[2], 0.f), fmaxf(a[3], 0.f));
                *(float2*)(out + (size_t)(gr0 + 8) * OUT_DIM + col) = o1;
            }
        }
    }
}

// ============================== launch =====================================
extern "C" void kernel_launch(void* const* d_in, const int* in_sizes, int n_in,
                              void* d_out, int out_size) {
    const float* x    = (const float*)d_in[0];
    const int*   rows = (const int*)  d_in[1];
    const int*   cols = (const int*)  d_in[2];
    const float* vals = (const float*)d_in[3];
    const float* W    = (const float*)d_in[4];
    float*       out  = (float*)d_out;

    const int n_nodes = in_sizes[0] / D_FEAT;
    const int n_edges = in_sizes[1];
    const int nb      = (n_nodes + CSR_BLK - 1) / CSR_BLK;   // 98 <= 148 SMs

    // fused CSR build (persistent, software grid barriers)
    csr_build_kernel<<<nb, CSR_BLK>>>(rows, cols, vals, W, n_nodes, n_edges, nb);

    // SpMM (warp per row)
    long long spmm_threads = (long long)n_nodes * 32;
    spmm_csr_kernel<<<(int)((spmm_threads + 255) / 256), 256>>>(x, n_nodes);

    // GEMM + relu
    cudaFuncSetAttribute(gemm_mma_kernel,
                         cudaFuncAttributeMaxDynamicSharedMemorySize, SM_TOTAL);
    gemm_mma_kernel<<<(n_nodes + TM - 1) / TM, GT, SM_TOTAL>>>(x, out, n_nodes);
}

// round 11
// speedup vs baseline: 1.0222x; 1.0222x over previous
#include <cuda_runtime.h>
#include <cuda_bf16.h>
#include <cstdint>

#define D_FEAT    128
#define OUT_DIM   128
#define MAX_NODES 100000
#define MAX_EDGES 600000
#define SCAN_BLK  1024
#define CNT_PAD   102400

#define TM   128          // rows per GEMM tile
#define CK   128          // K per chunk (2 chunks: h then x)
#define LDA  136          // padded bf16 row (272 B stride)
#define GT   256          // GEMM threads (8 warps)

// ---- device scratch (allocation-free) ----
__device__ float g_h[(size_t)MAX_NODES * D_FEAT];
__device__ __align__(16) int g_cnt[CNT_PAD];   // zero-init; self-cleaned each run
__device__ int   g_off[MAX_NODES + 1];
__device__ int   g_cur[MAX_NODES];
__device__ int   g_bsum[128];
__device__ int2  g_edge[MAX_EDGES];
__device__ int   g_bar_cnt;                    // grid barrier state (zero-init)
__device__ int   g_bar_gen;
// bf16 hi/lo images of B chunks: [chunk][part][n=128][k padded to LDA]
__device__ uint4 g_Bimg4[2 * 4352];   // 2 x 69632 B

// ============================ PTX helpers =================================
__device__ __forceinline__ uint32_t smem_u32(const void* p) {
    uint32_t a;
    asm("{ .reg .u64 t; cvta.to.shared.u64 t, %1; cvt.u32.u64 %0, t; }" : "=r"(a) : "l"(p));
    return a;
}
__device__ __forceinline__ void ldsm4(uint32_t* r, uint32_t addr) {
    asm volatile("ldmatrix.sync.aligned.m8n8.x4.shared.b16 {%0,%1,%2,%3}, [%4];"
                 : "=r"(r[0]), "=r"(r[1]), "=r"(r[2]), "=r"(r[3]) : "r"(addr));
}
__device__ __forceinline__ void mma_bf16(float* d, const uint32_t* a,
                                         uint32_t b0, uint32_t b1) {
    asm volatile(
        "mma.sync.aligned.m16n8k16.row.col.f32.bf16.bf16.f32 "
        "{%0,%1,%2,%3}, {%4,%5,%6,%7}, {%8,%9}, {%0,%1,%2,%3};"
        : "+f"(d[0]), "+f"(d[1]), "+f"(d[2]), "+f"(d[3])
        : "r"(a[0]), "r"(a[1]), "r"(a[2]), "r"(a[3]), "r"(b0), "r"(b1));
}
__device__ __forceinline__ uint32_t bf16x2(float y, float x) {
    uint32_t r; asm("cvt.rn.bf16x2.f32 %0, %1, %2;" : "=r"(r) : "f"(y), "f"(x)); return r;
}
__device__ __forceinline__ void cpa16(uint32_t dst, const void* src) {
    asm volatile("cp.async.cg.shared.global [%0], [%1], 16;" :: "r"(dst), "l"(src));
}
__device__ __forceinline__ void cpa16z(uint32_t dst, const void* src, int valid) {
    int sz = valid ? 16 : 0;
    asm volatile("cp.async.cg.shared.global [%0], [%1], 16, %2;"
                 :: "r"(dst), "l"(src), "r"(sz));
}
__device__ __forceinline__ void cpa_commit() {
    asm volatile("cp.async.commit_group;" ::: "memory");
}
template <int N>
__device__ __forceinline__ void cpa_wait() {
    asm volatile("cp.async.wait_group %0;" :: "n"(N) : "memory");
}

// ---- software grid barrier (all blocks co-resident: nb <= 148) ----
__device__ __forceinline__ void grid_bar(int nb) {
    __syncthreads();
    if (threadIdx.x == 0) {
        __threadfence();
        int gen = *(volatile int*)&g_bar_gen;
        if (atomicAdd(&g_bar_cnt, 1) == nb - 1) {
            g_bar_cnt = 0;
            __threadfence();
            *(volatile int*)&g_bar_gen = gen + 1;
        } else {
            while (*(volatile int*)&g_bar_gen == gen) { }
        }
        __threadfence();
    }
    __syncthreads();
}

// ============ hist + prep fused: edge histogram + B image build ============
__global__ void hist_prep_kernel(const int* __restrict__ rows,
                                 const float* __restrict__ W,
                                 int n, int n_edges) {
    int i = blockIdx.x * blockDim.x + threadIdx.x;
    if (i < 2 * 128 * 128) {
        int c = i >> 14;
        int r = i & 16383;
        int k = r >> 7;
        int nn = r & 127;
        float w = W[(size_t)(c * 128 + k) * OUT_DIM + nn];
        __nv_bfloat16 hb = __float2bfloat16(w);
        __nv_bfloat16 lb = __float2bfloat16(w - __bfloat162float(hb));
        __nv_bfloat16* img = (__nv_bfloat16*)g_Bimg4;
        img[(((size_t)c * 2 + 0) * 128 + nn) * LDA + k] = hb;
        img[(((size_t)c * 2 + 1) * 128 + nn) * LDA + k] = lb;
    }
    if (i < n_edges) atomicAdd(&g_cnt[rows[i]], 1);
}

// ====== fused scan: per-block totals | grid barrier | base + full scan =====
__global__ __launch_bounds__(SCAN_BLK, 1)
void scan_fused_kernel(int n, int nb, int n_edges) {
    __shared__ int wsum[32];
    __shared__ int sbase;
    const int t    = threadIdx.x;
    const int lane = t & 31;
    const int w    = t >> 5;
    const int i    = blockIdx.x * SCAN_BLK + t;

    // phase A: block-local inclusive scan (keeps v, s in regs) + block total
    int v = (i < n) ? g_cnt[i] : 0;
    int s = v;
#pragma unroll
    for (int d = 1; d < 32; d <<= 1) {
        int q = __shfl_up_sync(~0u, s, d);
        if (lane >= d) s += q;
    }
    if (lane == 31) wsum[w] = s;
    __syncthreads();
    if (w == 0) {
        int q = wsum[lane];
#pragma unroll
        for (int d = 1; d < 32; d <<= 1) {
            int r = __shfl_up_sync(~0u, q, d);
            if (lane >= d) q += r;
        }
        wsum[lane] = q;
    }
    __syncthreads();
    int wbase  = (w > 0) ? wsum[w - 1] : 0;
    int s_incl = wbase + s;
    if (t == SCAN_BLK - 1) g_bsum[blockIdx.x] = s_incl;

    grid_bar(nb);

    // phase B: base = sum of earlier block totals; write offsets/cursors
    if (w == 0) {
        int b = 0;
        for (int j = lane; j < (int)blockIdx.x; j += 32) b += g_bsum[j];
#pragma unroll
        for (int o = 16; o > 0; o >>= 1) b += __shfl_xor_sync(~0u, b, o);
        if (lane == 0) sbase = b;
    }
    __syncthreads();
    if (i < n) {
        int o = sbase + s_incl - v;
        g_off[i] = o;
        g_cur[i] = o;
        g_cnt[i] = 0;          // self-clean for next launch
    }
    if (i == n) g_off[n] = n_edges;
}

// ============ scatter: 2 edges/thread, atomics issued back-to-back =========
__global__ void scatter_kernel(const int* __restrict__ rows,
                               const int* __restrict__ cols,
                               const float* __restrict__ vals,
                               int n_edges) {
    int i = (blockIdx.x * blockDim.x + threadIdx.x) * 2;
    if (i + 1 < n_edges) {
        int r0 = rows[i], r1 = rows[i + 1];
        int c0 = cols[i], c1 = cols[i + 1];
        float v0 = vals[i], v1 = vals[i + 1];
        int p0 = atomicAdd(&g_cur[r0], 1);
        int p1 = atomicAdd(&g_cur[r1], 1);
        g_edge[p0] = make_int2(c0, __float_as_int(v0));
        g_edge[p1] = make_int2(c1, __float_as_int(v1));
    } else if (i < n_edges) {
        int p = atomicAdd(&g_cur[rows[i]], 1);
        g_edge[p] = make_int2(cols[i], __float_as_int(vals[i]));
    }
}

// ============ SpMM: warp per row, full occupancy, x4 unrolled ==============
__global__ void spmm_csr_kernel(const float* __restrict__ x, int n_nodes) {
    int row  = (blockIdx.x * blockDim.x + threadIdx.x) >> 5;
    int lane = threadIdx.x & 31;
    if (row >= n_nodes) return;

    int e  = g_off[row];
    int e1 = g_off[row + 1];

    float4 aA = make_float4(0.f, 0.f, 0.f, 0.f);
    float4 aB = make_float4(0.f, 0.f, 0.f, 0.f);
    for (; e + 4 <= e1; e += 4) {
        int2 e0 = g_edge[e],     e1v = g_edge[e + 1];
        int2 e2 = g_edge[e + 2], e3v = g_edge[e + 3];
        float4 x0 = ((const float4*)(x + (size_t)e0.x  * D_FEAT))[lane];
        float4 x1 = ((const float4*)(x + (size_t)e1v.x * D_FEAT))[lane];
        float4 x2 = ((const float4*)(x + (size_t)e2.x  * D_FEAT))[lane];
        float4 x3 = ((const float4*)(x + (size_t)e3v.x * D_FEAT))[lane];
        float v0 = __int_as_float(e0.y),  v1 = __int_as_float(e1v.y);
        float v2 = __int_as_float(e2.y),  v3 = __int_as_float(e3v.y);
        aA.x = fmaf(v0, x0.x, aA.x); aA.y = fmaf(v0, x0.y, aA.y);
        aA.z = fmaf(v0, x0.z, aA.z); aA.w = fmaf(v0, x0.w, aA.w);
        aB.x = fmaf(v1, x1.x, aB.x); aB.y = fmaf(v1, x1.y, aB.y);
        aB.z = fmaf(v1, x1.z, aB.z); aB.w = fmaf(v1, x1.w, aB.w);
        aA.x = fmaf(v2, x2.x, aA.x); aA.y = fmaf(v2, x2.y, aA.y);
        aA.z = fmaf(v2, x2.z, aA.z); aA.w = fmaf(v2, x2.w, aA.w);
        aB.x = fmaf(v3, x3.x, aB.x); aB.y = fmaf(v3, x3.y, aB.y);
        aB.z = fmaf(v3, x3.z, aB.z); aB.w = fmaf(v3, x3.w, aB.w);
    }
    for (; e < e1; e++) {
        int2 ev = g_edge[e];
        float4 xv = ((const float4*)(x + (size_t)ev.x * D_FEAT))[lane];
        float v = __int_as_float(ev.y);
        aA.x = fmaf(v, xv.x, aA.x); aA.y = fmaf(v, xv.y, aA.y);
        aA.z = fmaf(v, xv.z, aA.z); aA.w = fmaf(v, xv.w, aA.w);
    }
    float4 acc = make_float4(aA.x + aB.x, aA.y + aB.y, aA.z + aB.z, aA.w + aB.w);
    ((float4*)(g_h + (size_t)row * D_FEAT))[lane] = acc;
}

// ====== GEMM: out = relu([h|x] @ W), cp.async pipelined, 8 warps ==========
// smem: A hi (34816) | A lo (34816) | B hi+lo (69632) | x fp32 scratch (65536)
#define SM_A     0
#define SM_PART  34816
#define SM_B     69632
#define SM_X     139264
#define SM_TOTAL 204800

__global__ __launch_bounds__(GT, 1)
void gemm_mma_kernel(const float* __restrict__ x,
                     float* __restrict__ out,
                     int n_nodes) {
    extern __shared__ char smem[];
    const uint32_t sbase = smem_u32(smem);
    const int tid  = threadIdx.x;
    const int wid  = tid >> 5;
    const int lane = tid & 31;
    const int wm   = wid >> 1;       // 0..3  (32-row strip)
    const int wn   = wid & 1;        // 0..1  (64-col strip)
    const int row0 = blockIdx.x * TM;

    uint32_t pA[2], pB[4];
#pragma unroll
    for (int mf = 0; mf < 2; mf++)
        pA[mf] = sbase + SM_A
               + (uint32_t)((wm * 32 + mf * 16 + (lane & 15)) * (LDA * 2))
               + (uint32_t)((lane >> 4) << 4);
#pragma unroll
    for (int p = 0; p < 4; p++)
        pB[p] = sbase + SM_B
              + (uint32_t)((wn * 64 + p * 16 + (lane & 7) + ((lane >> 4) << 3)) * (LDA * 2))
              + (uint32_t)((lane & 8) << 1);

    float acc[2][8][4];
#pragma unroll
    for (int mf = 0; mf < 2; mf++)
#pragma unroll
        for (int nf = 0; nf < 8; nf++)
#pragma unroll
            for (int q = 0; q < 4; q++) acc[mf][nf][q] = 0.f;

    // ---- group 0: B chunk-0 image via cp.async ----
    {
        const uint4* sB = g_Bimg4;
#pragma unroll
        for (int j = tid; j < 4352; j += GT)
            cpa16(sbase + SM_B + j * 16, sB + j);
    }
    cpa_commit();
    // ---- group 1: x rows (chunk 1) fp32 -> scratch via cp.async ----
    {
#pragma unroll
        for (int j = 0; j < 4096 / GT; j++) {
            int i  = tid + j * GT;
            int r  = i >> 5;
            int kq = i & 31;
            int gr = row0 + r;
            cpa16z(sbase + SM_X + (uint32_t)(r * 512 + kq * 16),
                   x + (size_t)gr * D_FEAT + kq * 4, gr < n_nodes);
        }
    }
    cpa_commit();

    // ---- stage A chunk 0 from g_h (fp32 load, split bf16 hi/lo) ----
#pragma unroll
    for (int j = 0; j < (TM * CK / 4) / GT; j++) {
        int i  = tid + j * GT;
        int r  = i >> 5;
        int kq = i & 31;
        int gr = row0 + r;
        float4 v = make_float4(0.f, 0.f, 0.f, 0.f);
        if (gr < n_nodes) v = ((const float4*)(g_h + (size_t)gr * D_FEAT))[kq];
        uint32_t h01 = bf16x2(v.y, v.x);
        uint32_t h23 = bf16x2(v.w, v.z);
        float fx = __uint_as_float(h01 << 16);
        float fy = __uint_as_float(h01 & 0xffff0000u);
        float fz = __uint_as_float(h23 << 16);
        float fw = __uint_as_float(h23 & 0xffff0000u);
        uint32_t l01 = bf16x2(v.y - fy, v.x - fx);
        uint32_t l23 = bf16x2(v.w - fw, v.z - fz);
        char* dst = smem + SM_A + r * (LDA * 2) + kq * 8;
        *(uint2*)dst             = make_uint2(h01, h23);
        *(uint2*)(dst + SM_PART) = make_uint2(l01, l23);
    }
    cpa_wait<1>();
    __syncthreads();

    for (int c = 0; c < 2; c++) {
#pragma unroll
        for (int ks = 0; ks < CK / 16; ks++) {
            const uint32_t k0b = (uint32_t)(ks << 5);
            uint32_t Ah[2][4], Al[2][4];
#pragma unroll
            for (int mf = 0; mf < 2; mf++) {
                ldsm4(Ah[mf], pA[mf] + k0b);
                ldsm4(Al[mf], pA[mf] + SM_PART + k0b);
            }
            uint32_t Bh[4][4], Bl[4][4];
#pragma unroll
            for (int p = 0; p < 4; p++) {
                ldsm4(Bh[p], pB[p] + k0b);
                ldsm4(Bl[p], pB[p] + SM_PART + k0b);
            }
#pragma unroll
            for (int mf = 0; mf < 2; mf++)
#pragma unroll
                for (int p = 0; p < 4; p++) {
                    mma_bf16(acc[mf][2 * p],     Ah[mf], Bh[p][0], Bh[p][1]);
                    mma_bf16(acc[mf][2 * p + 1], Ah[mf], Bh[p][2], Bh[p][3]);
                    mma_bf16(acc[mf][2 * p],     Al[mf], Bh[p][0], Bh[p][1]);
                    mma_bf16(acc[mf][2 * p + 1], Al[mf], Bh[p][2], Bh[p][3]);
                    mma_bf16(acc[mf][2 * p],     Ah[mf], Bl[p][0], Bl[p][1]);
                    mma_bf16(acc[mf][2 * p + 1], Ah[mf], Bl[p][2], Bl[p][3]);
                }
        }

        if (c == 0) {
            cpa_wait<0>();
            __syncthreads();

            {
                const uint4* sB = g_Bimg4 + 4352;
#pragma unroll
                for (int j = tid; j < 4352; j += GT)
                    cpa16(sbase + SM_B + j * 16, sB + j);
            }
            cpa_commit();

#pragma unroll
            for (int j = 0; j < (TM * CK / 4) / GT; j++) {
                int i  = tid + j * GT;
                int r  = i >> 5;
                int kq = i & 31;
                float4 v = *(const float4*)(smem + SM_X + r * 512 + kq * 16);
                uint32_t h01 = bf16x2(v.y, v.x);
                uint32_t h23 = bf16x2(v.w, v.z);
                float fx = __uint_as_float(h01 << 16);
                float fy = __uint_as_float(h01 & 0xffff0000u);
                float fz = __uint_as_float(h23 << 16);
                float fw = __uint_as_float(h23 & 0xffff0000u);
                uint32_t l01 = bf16x2(v.y - fy, v.x - fx);
                uint32_t l23 = bf16x2(v.w - fw, v.z - fz);
                char* dst = smem + SM_A + r * (LDA * 2) + kq * 8;
                *(uint2*)dst             = make_uint2(h01, h23);
                *(uint2*)(dst + SM_PART) = make_uint2(l01, l23);
            }
            cpa_wait<0>();
            __syncthreads();
        }
    }

    // ---- epilogue: relu + store ----
#pragma unroll
    for (int mf = 0; mf < 2; mf++) {
        int gr0 = row0 + wm * 32 + mf * 16 + (lane >> 2);
#pragma unroll
        for (int nf = 0; nf < 8; nf++) {
            int col = wn * 64 + (nf >> 1) * 16 + (nf & 1) * 8 + (lane & 3) * 2;
            float* a = acc[mf][nf];
            if (gr0 < n_nodes) {
                float2 o0 = make_float2(fmaxf(a[0], 0.f), fmaxf(a[1], 0.f));
                *(float2*)(out + (size_t)gr0 * OUT_DIM + col) = o0;
            }
            if (gr0 + 8 < n_nodes) {
                float2 o1 = make_float2(fmaxf(a[2], 0.f), fmaxf(a[3], 0.f));
                *(float2*)(out + (size_t)(gr0 + 8) * OUT_DIM + col) = o1;
            }
        }
    }
}

// ============================== launch =====================================
extern "C" void kernel_launch(void* const* d_in, const int* in_sizes, int n_in,
                              void* d_out, int out_size) {
    const float* x    = (const float*)d_in[0];
    const int*   rows = (const int*)  d_in[1];
    const int*   cols = (const int*)  d_in[2];
    const float* vals = (const float*)d_in[3];
    const float* W    = (const float*)d_in[4];
    float*       out  = (float*)d_out;

    const int n_nodes = in_sizes[0] / D_FEAT;
    const int n_edges = in_sizes[1];
    const int nb      = (n_nodes + SCAN_BLK - 1) / SCAN_BLK;   // 98 <= 148

    hist_prep_kernel<<<(n_edges + 255) / 256, 256>>>(rows, W, n_nodes, n_edges);
    scan_fused_kernel<<<nb, SCAN_BLK>>>(n_nodes, nb, n_edges);
    scatter_kernel<<<(n_edges / 2 + 255) / 256, 256>>>(rows, cols, vals, n_edges);

    long long spmm_threads = (long long)n_nodes * 32;
    spmm_csr_kernel<<<(int)((spmm_threads + 255) / 256), 256>>>(x, n_nodes);

    cudaFuncSetAttribute(gemm_mma_kernel,
                         cudaFuncAttributeMaxDynamicSharedMemorySize, SM_TOTAL);
    gemm_mma_kernel<<<(n_nodes + TM - 1) / TM, GT, SM_TOTAL>>>(x, out, n_nodes);
}